// round 14
// baseline (speedup 1.0000x reference)
#include <cuda_runtime.h>
#include <cuda_fp16.h>
#include <cstdint>

#define NN 50000
#define NE 800000
#define NT (NE / 128)

// ---------------- device scratch ----------------
__device__ __align__(16) __half g_WPQh[128 * 256];
__device__ __align__(16) __half g_W3h[128 * 128];
__device__ __align__(16) float  g_BPQ[256];
__device__ __align__(16) __half g_PQh[(size_t)NN * 256];
__device__ int  g_cnt[NN];
__device__ int  g_cur[NN];
__device__ __align__(8) int2 g_e2[NE];   // packed (src, dst) per dst-sorted edge

// ---------------- helpers ----------------
__device__ __forceinline__ uint32_t smem_u32(const void* p) {
    uint32_t a;
    asm("{ .reg .u64 t; cvta.to.shared.u64 t, %1; cvt.u32.u64 %0, t; }" : "=r"(a) : "l"(p));
    return a;
}
__device__ __forceinline__ void ldsm_x4(uint32_t* r, uint32_t addr) {
    asm volatile("ldmatrix.sync.aligned.m8n8.x4.shared.b16 {%0,%1,%2,%3}, [%4];"
                 : "=r"(r[0]), "=r"(r[1]), "=r"(r[2]), "=r"(r[3]) : "r"(addr));
}
__device__ __forceinline__ void ldsm_x2t(uint32_t* r, uint32_t addr) {
    asm volatile("ldmatrix.sync.aligned.m8n8.x2.trans.shared.b16 {%0,%1}, [%2];"
                 : "=r"(r[0]), "=r"(r[1]) : "r"(addr));
}
__device__ __forceinline__ void mma16816(float* d, const uint32_t* a, const uint32_t* b) {
    asm volatile(
        "mma.sync.aligned.m16n8k16.row.col.f32.f16.f16.f32 "
        "{%0,%1,%2,%3}, {%4,%5,%6,%7}, {%8,%9}, {%0,%1,%2,%3};"
        : "+f"(d[0]), "+f"(d[1]), "+f"(d[2]), "+f"(d[3])
        : "r"(a[0]), "r"(a[1]), "r"(a[2]), "r"(a[3]), "r"(b[0]), "r"(b[1]));
}

// ---------------- init: zero out + zero cnt ----------------
__global__ void k_init(float4* out, int n4) {
    int i = blockIdx.x * blockDim.x + threadIdx.x;
    if (i < n4) out[i] = make_float4(0.f, 0.f, 0.f, 0.f);
    if (i < NN / 4) ((int4*)g_cnt)[i] = make_int4(0, 0, 0, 0);
}

// ---------------- weight prep ----------------
__global__ void k_prep_w(const float* __restrict__ W1, const float* __restrict__ b1,
                         const float* __restrict__ W2, const float* __restrict__ b2,
                         const float* __restrict__ W3) {
    int blk = blockIdx.x;
    if (blk >= 128) {
        int q = (blk - 128) * 256 + threadIdx.x;
        g_W3h[q] = __float2half_rn(W3[q]);
        return;
    }
    __shared__ float w1row[128];
    int i = blk;
    if (threadIdx.x < 128) w1row[threadIdx.x] = W1[i * 128 + threadIdx.x];
    __syncthreads();
    int j = threadIdx.x;
    float acc = 0.f;
    if (j < 128) {
        for (int k = 0; k < 128; k++)
            acc += w1row[k] * (W2[k * 128 + j] - W2[(k + 128) * 128 + j]);
    } else {
        int jj = j - 128;
        for (int k = 0; k < 128; k++)
            acc += w1row[k] * W2[(k + 128) * 128 + jj];
    }
    g_WPQh[i * 256 + j] = __float2half_rn(acc);
    if (i == 0) {
        float b = 0.f;
        if (j < 128) {
            for (int k = 0; k < 128; k++)
                b += b1[k] * (W2[k * 128 + j] - W2[(k + 128) * 128 + j]);
            b += b2[j];
        } else {
            int jj = j - 128;
            for (int k = 0; k < 128; k++)
                b += b1[k] * W2[(k + 128) * 128 + jj];
        }
        g_BPQ[j] = b;
    }
}

// ---------------- node GEMM (HMMA, A=x split hi/lo exact, B=WPQ fp16) ----------------
#define nAh 0u
#define nAl 16384u
#define nB  32768u
#define NODE_SMEM 98304

__global__ void __launch_bounds__(256, 2) k_node_hmma(const float* __restrict__ x) {
    extern __shared__ char smb[];
    uint32_t sb = smem_u32(smb);
    int tid = threadIdx.x, lane = tid & 31, wid = tid >> 5;
    int row0 = blockIdx.x * 64;

#pragma unroll
    for (int q = tid; q < 4096; q += 256) {
        int k = q >> 5, cj = q & 31;
        uint4 pk = ((const uint4*)g_WPQh)[q];
        *(uint4*)(smb + nB + (uint32_t)(k * 512) + (uint32_t)((cj ^ (k & 7)) << 4)) = pk;
    }
    {
        int r = tid & 63, hh = tid >> 6;
        int row = row0 + r;
        const float4* xp = (const float4*)(x + (size_t)row * 128 + hh * 32);
        uint32_t rowbase = (uint32_t)(r * 256);
#pragma unroll
        for (int c = 0; c < 4; c++) {
            float4 f0, f1;
            if (row < NN) { f0 = xp[c * 2]; f1 = xp[c * 2 + 1]; }
            else { f0 = make_float4(0, 0, 0, 0); f1 = f0; }
            float v[8] = {f0.x, f0.y, f0.z, f0.w, f1.x, f1.y, f1.z, f1.w};
            uint32_t hi[4], lo[4];
#pragma unroll
            for (int p = 0; p < 4; p++) {
                __half hx = __float2half_rn(v[p * 2]);
                __half hy = __float2half_rn(v[p * 2 + 1]);
                __half lx = __float2half_rn(v[p * 2] - __half2float(hx));
                __half ly = __float2half_rn(v[p * 2 + 1] - __half2float(hy));
                __half2 h2 = __halves2half2(hx, hy), l2 = __halves2half2(lx, ly);
                hi[p] = *(uint32_t*)&h2;
                lo[p] = *(uint32_t*)&l2;
            }
            int cj = hh * 4 + c;
            uint32_t off = rowbase + (uint32_t)((cj ^ (r & 7)) << 4);
            *(uint4*)(smb + nAh + off) = make_uint4(hi[0], hi[1], hi[2], hi[3]);
            *(uint4*)(smb + nAl + off) = make_uint4(lo[0], lo[1], lo[2], lo[3]);
        }
    }
    __syncthreads();

    int m0 = (wid & 1) * 32;
    int n0 = (wid >> 1) * 64;
    float acc[2][8][4];
#pragma unroll
    for (int a = 0; a < 2; a++)
#pragma unroll
        for (int b = 0; b < 8; b++)
#pragma unroll
            for (int c = 0; c < 4; c++) acc[a][b][c] = 0.f;

    int arow0 = m0 + (lane & 15), arow1 = arow0 + 16;
    int bk_lane = lane & 15;
#pragma unroll
    for (int ks = 0; ks < 8; ks++) {
        int chunk = ks * 2 + (lane >> 4);
        uint32_t a0a = sb + nAh + (uint32_t)(arow0 * 256) + (uint32_t)((chunk ^ (arow0 & 7)) << 4);
        uint32_t a1a = sb + nAh + (uint32_t)(arow1 * 256) + (uint32_t)((chunk ^ (arow1 & 7)) << 4);
        uint32_t ah0[4], ah1[4], al0[4], al1[4];
        ldsm_x4(ah0, a0a);
        ldsm_x4(ah1, a1a);
        ldsm_x4(al0, a0a + 16384u);
        ldsm_x4(al1, a1a + 16384u);
        int bk = ks * 16 + bk_lane;
        uint32_t brow = sb + nB + (uint32_t)(bk * 512);
        int bsw = bk & 7;
#pragma unroll
        for (int nt = 0; nt < 8; nt++) {
            uint32_t bfr[2];
            ldsm_x2t(bfr, brow + (uint32_t)((((n0 >> 3) + nt) ^ bsw) << 4));
            mma16816(acc[0][nt], ah0, bfr);
            mma16816(acc[1][nt], ah1, bfr);
            mma16816(acc[0][nt], al0, bfr);
            mma16816(acc[1][nt], al1, bfr);
        }
    }

    {
        int cc = 2 * (lane & 3), rr = lane >> 2;
#pragma unroll
        for (int nt = 0; nt < 8; nt++) {
            int c_ = n0 + nt * 8 + cc;
            float2 bb = *(const float2*)&g_BPQ[c_];
#pragma unroll
            for (int mt = 0; mt < 2; mt++) {
                int r_ = row0 + m0 + mt * 16 + rr;
                if (r_ < NN) {
                    __half2 h = __floats2half2_rn(acc[mt][nt][0] + bb.x, acc[mt][nt][1] + bb.y);
                    *(uint32_t*)&g_PQh[(size_t)r_ * 256 + c_] = *(uint32_t*)&h;
                }
                if (r_ + 8 < NN) {
                    __half2 h = __floats2half2_rn(acc[mt][nt][2] + bb.x, acc[mt][nt][3] + bb.y);
                    *(uint32_t*)&g_PQh[(size_t)(r_ + 8) * 256 + c_] = *(uint32_t*)&h;
                }
            }
        }
    }
}

// ---------------- CSR build ----------------
__global__ void k_hist(const int* __restrict__ ei) {
    int e = blockIdx.x * blockDim.x + threadIdx.x;
    if (e < NE) atomicAdd(&g_cnt[ei[NE + e]], 1);
}
__global__ void k_scan() {
    __shared__ int s[1024];
    const int CH = 49;
    int t = threadIdx.x;
    int start = t * CH;
    int sum = 0;
    for (int i = 0; i < CH; i++) {
        int idx = start + i;
        if (idx < NN) sum += g_cnt[idx];
    }
    s[t] = sum;
    __syncthreads();
    for (int d = 1; d < 1024; d <<= 1) {
        int v = (t >= d) ? s[t - d] : 0;
        __syncthreads();
        s[t] += v;
        __syncthreads();
    }
    int run = s[t] - sum;
    for (int i = 0; i < CH; i++) {
        int idx = start + i;
        if (idx < NN) {
            g_cur[idx] = run;
            run += g_cnt[idx];
        }
    }
}
__global__ void k_scatter(const int* __restrict__ ei) {
    int e = blockIdx.x * blockDim.x + threadIdx.x;
    if (e < NE) {
        int d = ei[NE + e];
        int sr = ei[e];
        int pos = atomicAdd(&g_cur[d], 1);
        g_e2[pos] = make_int2(sr, d);
    }
}

// ---------------- persistent pipelined HMMA edge kernel ----------------
// smem: A0 @0 (32K), A1 @32768 (32K), B @65536 (32K), b3s @98304 (512), sd[2][128] @98816 (1K)
// Epilogue fully in registers (warp-shuffle segmented max) — no smem round trip.
#define oA   0u
#define oB   65536u
#define oB3  98304u
#define oSD  98816u
#define EDGE_SMEM 99840

__device__ __forceinline__ void edge_build(int t, uint32_t abase, int sdoff,
                                           char* smb, int tid) {
    int r = tid & 127, hh = tid >> 7;
    int e = t * 128 + r;
    int2 sd2 = g_e2[e];
    int src = sd2.x, dst = sd2.y;
    if (hh == 0) ((int*)(smb + oSD))[sdoff + r] = dst;
    const uint4* pv = (const uint4*)(g_PQh + (size_t)dst * 256);
    const uint4* qv = (const uint4*)(g_PQh + (size_t)src * 256);
    uint32_t rowbase = abase + (uint32_t)(r * 256);
    const __half2 z = __float2half2_rn(0.f);
#pragma unroll
    for (int c = 0; c < 8; c++) {
        uint4 pk = pv[hh * 8 + c];
        uint4 qk = qv[16 + hh * 8 + c];
        __half2 s0 = __hmax2(__hadd2(*(__half2*)&pk.x, *(__half2*)&qk.x), z);
        __half2 s1 = __hmax2(__hadd2(*(__half2*)&pk.y, *(__half2*)&qk.y), z);
        __half2 s2 = __hmax2(__hadd2(*(__half2*)&pk.z, *(__half2*)&qk.z), z);
        __half2 s3 = __hmax2(__hadd2(*(__half2*)&pk.w, *(__half2*)&qk.w), z);
        int cj = hh * 8 + c;
        *(uint4*)(smb + rowbase + (uint32_t)((cj ^ (r & 7)) << 4)) =
            make_uint4(*(uint32_t*)&s0, *(uint32_t*)&s1, *(uint32_t*)&s2, *(uint32_t*)&s3);
    }
}

__global__ void __launch_bounds__(256, 2) k_edge_pers(const float* __restrict__ b3,
                                                      float* __restrict__ out) {
    extern __shared__ char smb[];
    uint32_t sb = smem_u32(smb);
    int tid = threadIdx.x, lane = tid & 31, wid = tid >> 5;

    if (tid < 128) ((float*)(smb + oB3))[tid] = b3[tid];
    // stage B once per CTA
#pragma unroll
    for (int q = tid; q < 2048; q += 256) {
        int k = q >> 4, cj = q & 15;
        uint4 pk = ((const uint4*)g_W3h)[q];
        *(uint4*)(smb + oB + (uint32_t)(k * 256) + (uint32_t)((cj ^ (k & 7)) << 4)) = pk;
    }

    int m0 = (wid & 3) * 32;
    int n0 = (wid >> 2) * 64;
    int arow0 = m0 + (lane & 15), arow1 = arow0 + 16;
    int bk_lane = lane & 15;
    int a0sw = arow0 & 7, a1sw = arow1 & 7;
    int rr4 = lane >> 2, cc = 2 * (lane & 3);

    int t = blockIdx.x;
    if (t < NT) edge_build(t, oA, 0, smb, tid);   // prologue into buf 0

    int it = 0;
    for (; t < NT; t += gridDim.x, it ^= 1) {
        uint32_t abase = oA + (uint32_t)it * 32768u;
        int sdoff = it * 128;
        __syncthreads();   // A[it]/sd[it] built; prior iteration fully consumed

        // ---- MMA from A[it] ----
        float acc[2][8][4];
#pragma unroll
        for (int a = 0; a < 2; a++)
#pragma unroll
            for (int b = 0; b < 8; b++)
#pragma unroll
                for (int c = 0; c < 4; c++) acc[a][b][c] = 0.f;
        uint32_t a0base = sb + abase + (uint32_t)(arow0 * 256);
        uint32_t a1base = sb + abase + (uint32_t)(arow1 * 256);
#pragma unroll
        for (int ks = 0; ks < 8; ks++) {
            int chunk = ks * 2 + (lane >> 4);
            uint32_t ah0[4], ah1[4];
            ldsm_x4(ah0, a0base + (uint32_t)((chunk ^ a0sw) << 4));
            ldsm_x4(ah1, a1base + (uint32_t)((chunk ^ a1sw) << 4));
            int bk = ks * 16 + bk_lane;
            uint32_t brow = sb + oB + (uint32_t)(bk * 256);
            int bsw = bk & 7;
#pragma unroll
            for (int nt = 0; nt < 8; nt++) {
                uint32_t bfr[2];
                ldsm_x2t(bfr, brow + (uint32_t)((((n0 >> 3) + nt) ^ bsw) << 4));
                mma16816(acc[0][nt], ah0, bfr);
                mma16816(acc[1][nt], ah1, bfr);
            }
        }

        // ---- build next tile into A[it^1]/sd[it^1] (hides LDG under epilogue) ----
        int tn = t + gridDim.x;
        if (tn < NT) edge_build(tn, oA + (uint32_t)(it ^ 1) * 32768u, (it ^ 1) * 128, smb, tid);

        // ---- in-register epilogue: bias+relu, shuffle segmented max, atomicMax tails ----
        {
            const float* b3s = (const float*)(smb + oB3);
            const int* sd = (const int*)(smb + oSD) + sdoff;
            // bias + relu in place
#pragma unroll
            for (int nt = 0; nt < 8; nt++) {
                float2 bb = *(const float2*)&b3s[n0 + nt * 8 + cc];
#pragma unroll
                for (int mt = 0; mt < 2; mt++) {
                    acc[mt][nt][0] = fmaxf(acc[mt][nt][0] + bb.x, 0.f);
                    acc[mt][nt][1] = fmaxf(acc[mt][nt][1] + bb.y, 0.f);
                    acc[mt][nt][2] = fmaxf(acc[mt][nt][2] + bb.x, 0.f);
                    acc[mt][nt][3] = fmaxf(acc[mt][nt][3] + bb.y, 0.f);
                }
            }
            // 4 row-groups of 8 sorted rows each: rows m0 + g*8 + rr4
#pragma unroll
            for (int g = 0; g < 4; g++) {
                int mt = g >> 1, co = (g & 1) * 2;
                int d = sd[m0 + g * 8 + rr4];
                int pd = __shfl_up_sync(0xFFFFFFFFu, d, 4);
                bool head = (rr4 == 0) || (d != pd);
                unsigned hm = __ballot_sync(0xFFFFFFFFu, head);
                unsigned lm = 0xFFFFFFFFu >> (31 - lane);
                int head_lane = 31 - __clz(hm & lm);
                int rel = rr4 - (head_lane >> 2);   // rows since segment head (row space!)
#pragma unroll
                for (int s = 1; s < 8; s <<= 1) {
                    bool take = rel >= s;
#pragma unroll
                    for (int nt = 0; nt < 8; nt++) {
                        float o0 = __shfl_up_sync(0xFFFFFFFFu, acc[mt][nt][co], s * 4);
                        float o1 = __shfl_up_sync(0xFFFFFFFFu, acc[mt][nt][co + 1], s * 4);
                        if (take) {
                            acc[mt][nt][co] = fmaxf(acc[mt][nt][co], o0);
                            acc[mt][nt][co + 1] = fmaxf(acc[mt][nt][co + 1], o1);
                        }
                    }
                }
                int nd = __shfl_down_sync(0xFFFFFFFFu, d, 4);
                bool tail = (rr4 == 7) || (d != nd);
                if (tail) {
                    int* op = (int*)out + (size_t)d * 128 + n0 + cc;
#pragma unroll
                    for (int nt = 0; nt < 8; nt++) {
                        float v0 = acc[mt][nt][co], v1 = acc[mt][nt][co + 1];
                        if (v0 > 0.f) atomicMax(op + nt * 8, __float_as_int(v0));
                        if (v1 > 0.f) atomicMax(op + nt * 8 + 1, __float_as_int(v1));
                    }
                }
            }
        }
    }
}

// ---------------- launch: CSR chain forked onto a side stream ----------------
extern "C" void kernel_launch(void* const* d_in, const int* in_sizes, int n_in,
                              void* d_out, int out_size) {
    const float* x  = (const float*)d_in[0];
    const int*   ei = (const int*)d_in[1];
    const float* W1 = (const float*)d_in[2];
    const float* b1 = (const float*)d_in[3];
    const float* W2 = (const float*)d_in[4];
    const float* b2 = (const float*)d_in[5];
    const float* W3 = (const float*)d_in[6];
    const float* b3 = (const float*)d_in[7];
    float* out = (float*)d_out;

    static cudaStream_t s2 = nullptr;
    static cudaEvent_t evFork = nullptr, evCsr = nullptr;
    static int grid2 = 0;
    if (!s2) {
        cudaStreamCreateWithFlags(&s2, cudaStreamNonBlocking);
        cudaEventCreateWithFlags(&evFork, cudaEventDisableTiming);
        cudaEventCreateWithFlags(&evCsr, cudaEventDisableTiming);
        int nsm = 0;
        cudaDeviceGetAttribute(&nsm, cudaDevAttrMultiProcessorCount, 0);
        grid2 = 2 * nsm;
        cudaFuncSetAttribute(k_edge_pers, cudaFuncAttributeMaxDynamicSharedMemorySize, EDGE_SMEM);
        cudaFuncSetAttribute(k_node_hmma, cudaFuncAttributeMaxDynamicSharedMemorySize, NODE_SMEM);
    }

    // default stream: init (zero out + cnt)
    k_init<<<(NN * 128 / 4 + 255) / 256, 256>>>((float4*)out, NN * 128 / 4);

    // fork: CSR chain on s2
    cudaEventRecord(evFork, 0);
    cudaStreamWaitEvent(s2, evFork, 0);
    k_hist<<<NE / 256, 256, 0, s2>>>(ei);
    k_scan<<<1, 1024, 0, s2>>>();
    k_scatter<<<NE / 256, 256, 0, s2>>>(ei);
    cudaEventRecord(evCsr, s2);

    // default stream: weights -> node GEMM (concurrent with CSR)
    k_prep_w<<<192, 256>>>(W1, b1, W2, b2, W3);
    k_node_hmma<<<(NN + 63) / 64, 256, NODE_SMEM>>>(x);

    // join: edge GEMM needs both PQ and CSR
    cudaStreamWaitEvent(0, evCsr, 0);
    k_edge_pers<<<grid2, 256, EDGE_SMEM>>>(b3, out);
}

// round 16
// speedup vs baseline: 1.1821x; 1.1821x over previous
#include <cuda_runtime.h>
#include <cuda_fp16.h>
#include <cstdint>

#define NN 50000
#define NE 800000
#define NT (NE / 128)

// ---------------- device scratch ----------------
__device__ __align__(16) __half g_WPQh[128 * 256];
__device__ __align__(16) __half g_W3h[128 * 128];
__device__ __align__(16) float  g_BPQ[256];
__device__ __align__(16) __half g_PQh[(size_t)NN * 256];
__device__ int  g_cnt[NN];       // zero at load; re-zeroed by k_scatter each run
__device__ int  g_cur[NN];
__device__ __align__(8) int2 g_e2[NE];

// ---------------- helpers ----------------
__device__ __forceinline__ uint32_t smem_u32(const void* p) {
    uint32_t a;
    asm("{ .reg .u64 t; cvta.to.shared.u64 t, %1; cvt.u32.u64 %0, t; }" : "=r"(a) : "l"(p));
    return a;
}
__device__ __forceinline__ void ldsm_x4(uint32_t* r, uint32_t addr) {
    asm volatile("ldmatrix.sync.aligned.m8n8.x4.shared.b16 {%0,%1,%2,%3}, [%4];"
                 : "=r"(r[0]), "=r"(r[1]), "=r"(r[2]), "=r"(r[3]) : "r"(addr));
}
__device__ __forceinline__ void ldsm_x2t(uint32_t* r, uint32_t addr) {
    asm volatile("ldmatrix.sync.aligned.m8n8.x2.trans.shared.b16 {%0,%1}, [%2];"
                 : "=r"(r[0]), "=r"(r[1]) : "r"(addr));
}
__device__ __forceinline__ void mma16816(float* d, const uint32_t* a, const uint32_t* b) {
    asm volatile(
        "mma.sync.aligned.m16n8k16.row.col.f32.f16.f16.f32 "
        "{%0,%1,%2,%3}, {%4,%5,%6,%7}, {%8,%9}, {%0,%1,%2,%3};"
        : "+f"(d[0]), "+f"(d[1]), "+f"(d[2]), "+f"(d[3])
        : "r"(a[0]), "r"(a[1]), "r"(a[2]), "r"(a[3]), "r"(b[0]), "r"(b[1]));
}

// ---------------- init: zero out + dst histogram (g_cnt pre-zeroed) ----------------
__global__ void k_init(float4* out, int n4, const int* __restrict__ ei) {
    int i = blockIdx.x * blockDim.x + threadIdx.x;
    if (i < n4) out[i] = make_float4(0.f, 0.f, 0.f, 0.f);
    if (i < NE) atomicAdd(&g_cnt[ei[NE + i]], 1);
}

// ---------------- weight prep ----------------
__global__ void k_prep_w(const float* __restrict__ W1, const float* __restrict__ b1,
                         const float* __restrict__ W2, const float* __restrict__ b2,
                         const float* __restrict__ W3) {
    int blk = blockIdx.x;
    if (blk >= 128) {
        int q = (blk - 128) * 256 + threadIdx.x;
        g_W3h[q] = __float2half_rn(W3[q]);
        return;
    }
    __shared__ float w1row[128];
    int i = blk;
    if (threadIdx.x < 128) w1row[threadIdx.x] = W1[i * 128 + threadIdx.x];
    __syncthreads();
    int j = threadIdx.x;
    float acc = 0.f;
    if (j < 128) {
        for (int k = 0; k < 128; k++)
            acc += w1row[k] * (W2[k * 128 + j] - W2[(k + 128) * 128 + j]);
    } else {
        int jj = j - 128;
        for (int k = 0; k < 128; k++)
            acc += w1row[k] * W2[(k + 128) * 128 + jj];
    }
    g_WPQh[i * 256 + j] = __float2half_rn(acc);
    if (i == 0) {
        float b = 0.f;
        if (j < 128) {
            for (int k = 0; k < 128; k++)
                b += b1[k] * (W2[k * 128 + j] - W2[(k + 128) * 128 + j]);
            b += b2[j];
        } else {
            int jj = j - 128;
            for (int k = 0; k < 128; k++)
                b += b1[k] * W2[(k + 128) * 128 + jj];
        }
        g_BPQ[j] = b;
    }
}

// ---------------- node GEMM (HMMA, A=x split hi/lo exact, B=WPQ fp16) ----------------
#define nAh 0u
#define nAl 16384u
#define nB  32768u
#define NODE_SMEM 98304

__global__ void __launch_bounds__(256, 2) k_node_hmma(const float* __restrict__ x) {
    extern __shared__ char smb[];
    uint32_t sb = smem_u32(smb);
    int tid = threadIdx.x, lane = tid & 31, wid = tid >> 5;
    int row0 = blockIdx.x * 64;

#pragma unroll
    for (int q = tid; q < 4096; q += 256) {
        int k = q >> 5, cj = q & 31;
        uint4 pk = ((const uint4*)g_WPQh)[q];
        *(uint4*)(smb + nB + (uint32_t)(k * 512) + (uint32_t)((cj ^ (k & 7)) << 4)) = pk;
    }
    {
        int r = tid & 63, hh = tid >> 6;
        int row = row0 + r;
        const float4* xp = (const float4*)(x + (size_t)row * 128 + hh * 32);
        uint32_t rowbase = (uint32_t)(r * 256);
#pragma unroll
        for (int c = 0; c < 4; c++) {
            float4 f0, f1;
            if (row < NN) { f0 = xp[c * 2]; f1 = xp[c * 2 + 1]; }
            else { f0 = make_float4(0, 0, 0, 0); f1 = f0; }
            float v[8] = {f0.x, f0.y, f0.z, f0.w, f1.x, f1.y, f1.z, f1.w};
            uint32_t hi[4], lo[4];
#pragma unroll
            for (int p = 0; p < 4; p++) {
                __half hx = __float2half_rn(v[p * 2]);
                __half hy = __float2half_rn(v[p * 2 + 1]);
                __half lx = __float2half_rn(v[p * 2] - __half2float(hx));
                __half ly = __float2half_rn(v[p * 2 + 1] - __half2float(hy));
                __half2 h2 = __halves2half2(hx, hy), l2 = __halves2half2(lx, ly);
                hi[p] = *(uint32_t*)&h2;
                lo[p] = *(uint32_t*)&l2;
            }
            int cj = hh * 4 + c;
            uint32_t off = rowbase + (uint32_t)((cj ^ (r & 7)) << 4);
            *(uint4*)(smb + nAh + off) = make_uint4(hi[0], hi[1], hi[2], hi[3]);
            *(uint4*)(smb + nAl + off) = make_uint4(lo[0], lo[1], lo[2], lo[3]);
        }
    }
    __syncthreads();

    int m0 = (wid & 1) * 32;
    int n0 = (wid >> 1) * 64;
    float acc[2][8][4];
#pragma unroll
    for (int a = 0; a < 2; a++)
#pragma unroll
        for (int b = 0; b < 8; b++)
#pragma unroll
            for (int c = 0; c < 4; c++) acc[a][b][c] = 0.f;

    int arow0 = m0 + (lane & 15), arow1 = arow0 + 16;
    int bk_lane = lane & 15;
#pragma unroll
    for (int ks = 0; ks < 8; ks++) {
        int chunk = ks * 2 + (lane >> 4);
        uint32_t a0a = sb + nAh + (uint32_t)(arow0 * 256) + (uint32_t)((chunk ^ (arow0 & 7)) << 4);
        uint32_t a1a = sb + nAh + (uint32_t)(arow1 * 256) + (uint32_t)((chunk ^ (arow1 & 7)) << 4);
        uint32_t ah0[4], ah1[4], al0[4], al1[4];
        ldsm_x4(ah0, a0a);
        ldsm_x4(ah1, a1a);
        ldsm_x4(al0, a0a + 16384u);
        ldsm_x4(al1, a1a + 16384u);
        int bk = ks * 16 + bk_lane;
        uint32_t brow = sb + nB + (uint32_t)(bk * 512);
        int bsw = bk & 7;
#pragma unroll
        for (int nt = 0; nt < 8; nt++) {
            uint32_t bfr[2];
            ldsm_x2t(bfr, brow + (uint32_t)((((n0 >> 3) + nt) ^ bsw) << 4));
            mma16816(acc[0][nt], ah0, bfr);
            mma16816(acc[1][nt], ah1, bfr);
            mma16816(acc[0][nt], al0, bfr);
            mma16816(acc[1][nt], al1, bfr);
        }
    }

    {
        int cc = 2 * (lane & 3), rr = lane >> 2;
#pragma unroll
        for (int nt = 0; nt < 8; nt++) {
            int c_ = n0 + nt * 8 + cc;
            float2 bb = *(const float2*)&g_BPQ[c_];
#pragma unroll
            for (int mt = 0; mt < 2; mt++) {
                int r_ = row0 + m0 + mt * 16 + rr;
                if (r_ < NN) {
                    __half2 h = __floats2half2_rn(acc[mt][nt][0] + bb.x, acc[mt][nt][1] + bb.y);
                    *(uint32_t*)&g_PQh[(size_t)r_ * 256 + c_] = *(uint32_t*)&h;
                }
                if (r_ + 8 < NN) {
                    __half2 h = __floats2half2_rn(acc[mt][nt][2] + bb.x, acc[mt][nt][3] + bb.y);
                    *(uint32_t*)&g_PQh[(size_t)(r_ + 8) * 256 + c_] = *(uint32_t*)&h;
                }
            }
        }
    }
}

// ---------------- CSR scan + scatter ----------------
__global__ void k_scan() {
    __shared__ int s[1024];
    const int CH = 49;
    int t = threadIdx.x;
    int start = t * CH;
    int sum = 0;
    for (int i = 0; i < CH; i++) {
        int idx = start + i;
        if (idx < NN) sum += g_cnt[idx];
    }
    s[t] = sum;
    __syncthreads();
    for (int d = 1; d < 1024; d <<= 1) {
        int v = (t >= d) ? s[t - d] : 0;
        __syncthreads();
        s[t] += v;
        __syncthreads();
    }
    int run = s[t] - sum;
    for (int i = 0; i < CH; i++) {
        int idx = start + i;
        if (idx < NN) {
            g_cur[idx] = run;
            run += g_cnt[idx];
        }
    }
}
__global__ void k_scatter(const int* __restrict__ ei) {
    int e = blockIdx.x * blockDim.x + threadIdx.x;
    if (e < NE) {
        int d = ei[NE + e];
        int sr = ei[e];
        int pos = atomicAdd(&g_cur[d], 1);
        g_e2[pos] = make_int2(sr, d);
    }
    if (e < NN) g_cnt[e] = 0;   // restore invariant for next graph replay
}

// ---------------- persistent pipelined HMMA edge kernel (race-free) ----------------
// smem: A0 @0 (32K), A1 @32768 (32K), B @65536 (32K), b3s @98304 (512), sd[2][128] @98816 (1K)
// accf(half, [128][128], swizzled) overlays the DEAD A buffer each iteration.
// Critical ordering per tile:
//   sync -> MMA(A[it]) -> build(A[it^1]) -> SYNC (all MMA reads of A[it] done!)
//   -> dump into A[it] -> sync -> epilogue
#define oA   0u
#define oB   65536u
#define oB3  98304u
#define oSD  98816u
#define EDGE_SMEM 99840

__device__ __forceinline__ void edge_build(int2 sd2, uint32_t abase, int sdoff,
                                           char* smb, int tid) {
    int r = tid & 127, hh = tid >> 7;
    int src = sd2.x, dst = sd2.y;
    if (hh == 0) ((int*)(smb + oSD))[sdoff + r] = dst;
    const uint4* pv = (const uint4*)(g_PQh + (size_t)dst * 256);
    const uint4* qv = (const uint4*)(g_PQh + (size_t)src * 256);
    uint32_t rowbase = abase + (uint32_t)(r * 256);
    const __half2 z = __float2half2_rn(0.f);
#pragma unroll
    for (int c = 0; c < 8; c++) {
        uint4 pk = pv[hh * 8 + c];
        uint4 qk = qv[16 + hh * 8 + c];
        __half2 s0 = __hmax2(__hadd2(*(__half2*)&pk.x, *(__half2*)&qk.x), z);
        __half2 s1 = __hmax2(__hadd2(*(__half2*)&pk.y, *(__half2*)&qk.y), z);
        __half2 s2 = __hmax2(__hadd2(*(__half2*)&pk.z, *(__half2*)&qk.z), z);
        __half2 s3 = __hmax2(__hadd2(*(__half2*)&pk.w, *(__half2*)&qk.w), z);
        int cj = hh * 8 + c;
        *(uint4*)(smb + rowbase + (uint32_t)((cj ^ (r & 7)) << 4)) =
            make_uint4(*(uint32_t*)&s0, *(uint32_t*)&s1, *(uint32_t*)&s2, *(uint32_t*)&s3);
    }
}

__global__ void __launch_bounds__(256, 2) k_edge_pers(const float* __restrict__ b3,
                                                      float* __restrict__ out) {
    extern __shared__ char smb[];
    uint32_t sb = smem_u32(smb);
    int tid = threadIdx.x, lane = tid & 31, wid = tid >> 5;

    if (tid < 128) ((float*)(smb + oB3))[tid] = b3[tid];
    // stage B once per CTA
#pragma unroll
    for (int q = tid; q < 2048; q += 256) {
        int k = q >> 4, cj = q & 15;
        uint4 pk = ((const uint4*)g_W3h)[q];
        *(uint4*)(smb + oB + (uint32_t)(k * 256) + (uint32_t)((cj ^ (k & 7)) << 4)) = pk;
    }

    int m0 = (wid & 3) * 32;
    int n0 = (wid >> 2) * 64;
    int arow0 = m0 + (lane & 15), arow1 = arow0 + 16;
    int bk_lane = lane & 15;
    int a0sw = arow0 & 7, a1sw = arow1 & 7;
    int rr = lane >> 2, cc = 2 * (lane & 3);
    int er = tid & 127;

    int t = blockIdx.x;
    if (t < NT) edge_build(g_e2[t * 128 + er], oA, 0, smb, tid);   // prologue into buf 0

    int it = 0;
    for (; t < NT; t += gridDim.x, it ^= 1) {
        uint32_t abase = oA + (uint32_t)it * 32768u;
        int sdoff = it * 128;
        __syncthreads();   // A[it]/sd[it] built; prior epilogue done

        // prefetch next tile's edge pair BEFORE the MMA
        int tn = t + gridDim.x;
        int2 sd2n = make_int2(0, 0);
        if (tn < NT) sd2n = g_e2[tn * 128 + er];

        // ---- MMA from A[it] ----
        float acc[2][8][4];
#pragma unroll
        for (int a = 0; a < 2; a++)
#pragma unroll
            for (int b = 0; b < 8; b++)
#pragma unroll
                for (int c = 0; c < 4; c++) acc[a][b][c] = 0.f;
        uint32_t a0base = sb + abase + (uint32_t)(arow0 * 256);
        uint32_t a1base = sb + abase + (uint32_t)(arow1 * 256);
#pragma unroll
        for (int ks = 0; ks < 8; ks++) {
            int chunk = ks * 2 + (lane >> 4);
            uint32_t ah0[4], ah1[4];
            ldsm_x4(ah0, a0base + (uint32_t)((chunk ^ a0sw) << 4));
            ldsm_x4(ah1, a1base + (uint32_t)((chunk ^ a1sw) << 4));
            int bk = ks * 16 + bk_lane;
            uint32_t brow = sb + oB + (uint32_t)(bk * 256);
            int bsw = bk & 7;
#pragma unroll
            for (int nt = 0; nt < 8; nt++) {
                uint32_t bfr[2];
                ldsm_x2t(bfr, brow + (uint32_t)((((n0 >> 3) + nt) ^ bsw) << 4));
                mma16816(acc[0][nt], ah0, bfr);
                mma16816(acc[1][nt], ah1, bfr);
            }
        }

        // ---- build next tile into A[it^1] (overlaps MMA latency drain) ----
        if (tn < NT) edge_build(sd2n, oA + (uint32_t)(it ^ 1) * 32768u, (it ^ 1) * 128, smb, tid);

        __syncthreads();   // ALL warps' MMA reads of A[it] complete before dump overwrites it

        // ---- dump acc as fp16 into A[it] (dead now; swizzled) ----
        {
#pragma unroll
            for (int mt = 0; mt < 2; mt++)
#pragma unroll
                for (int nt = 0; nt < 8; nt++) {
                    int r_ = m0 + mt * 16 + rr;
                    uint32_t c2 = (uint32_t)((n0 + nt * 8 + cc) * 2);
                    __half2 h0 = __floats2half2_rn(acc[mt][nt][0], acc[mt][nt][1]);
                    __half2 h1 = __floats2half2_rn(acc[mt][nt][2], acc[mt][nt][3]);
                    *(uint32_t*)(smb + abase + (uint32_t)(r_ * 256) +
                                 (c2 ^ ((uint32_t)(r_ & 7) << 4))) = *(uint32_t*)&h0;
                    *(uint32_t*)(smb + abase + (uint32_t)((r_ + 8) * 256) +
                                 (c2 ^ ((uint32_t)((r_ + 8) & 7) << 4))) = *(uint32_t*)&h1;
                }
        }
        __syncthreads();

        // ---- epilogue: bias + relu + run-merged segmented max + atomicMax ----
        {
            int cg = tid & 31;
            int rg = tid >> 5;
            const float* b3s = (const float*)(smb + oB3);
            const int* sd = (const int*)(smb + oSD) + sdoff;
            float4 bias = *(const float4*)&b3s[cg * 4];
            int rbase = rg * 16;
            int curd = sd[rbase];
            float4 mx;
            {
                uint2 hv = *(uint2*)(smb + abase + (uint32_t)(rbase * 256) +
                                     (((uint32_t)cg * 8) ^ ((uint32_t)(rbase & 7) << 4)));
                float2 f01 = __half22float2(*(__half2*)&hv.x);
                float2 f23 = __half22float2(*(__half2*)&hv.y);
                mx = make_float4(fmaxf(f01.x + bias.x, 0.f), fmaxf(f01.y + bias.y, 0.f),
                                 fmaxf(f23.x + bias.z, 0.f), fmaxf(f23.y + bias.w, 0.f));
            }
#pragma unroll
            for (int i = 1; i < 16; i++) {
                int row = rbase + i;
                int d = sd[row];
                uint2 hv = *(uint2*)(smb + abase + (uint32_t)(row * 256) +
                                     (((uint32_t)cg * 8) ^ ((uint32_t)(row & 7) << 4)));
                float2 f01 = __half22float2(*(__half2*)&hv.x);
                float2 f23 = __half22float2(*(__half2*)&hv.y);
                float4 w = make_float4(fmaxf(f01.x + bias.x, 0.f), fmaxf(f01.y + bias.y, 0.f),
                                       fmaxf(f23.x + bias.z, 0.f), fmaxf(f23.y + bias.w, 0.f));
                if (d != curd) {
                    int* op = (int*)out + (size_t)curd * 128 + cg * 4;
                    if (mx.x > 0.f) atomicMax(op + 0, __float_as_int(mx.x));
                    if (mx.y > 0.f) atomicMax(op + 1, __float_as_int(mx.y));
                    if (mx.z > 0.f) atomicMax(op + 2, __float_as_int(mx.z));
                    if (mx.w > 0.f) atomicMax(op + 3, __float_as_int(mx.w));
                    curd = d;
                    mx = w;
                } else {
                    mx.x = fmaxf(mx.x, w.x);
                    mx.y = fmaxf(mx.y, w.y);
                    mx.z = fmaxf(mx.z, w.z);
                    mx.w = fmaxf(mx.w, w.w);
                }
            }
            int* op = (int*)out + (size_t)curd * 128 + cg * 4;
            if (mx.x > 0.f) atomicMax(op + 0, __float_as_int(mx.x));
            if (mx.y > 0.f) atomicMax(op + 1, __float_as_int(mx.y));
            if (mx.z > 0.f) atomicMax(op + 2, __float_as_int(mx.z));
            if (mx.w > 0.f) atomicMax(op + 3, __float_as_int(mx.w));
        }
    }
}

// ---------------- launch: CSR chain forked onto a side stream ----------------
extern "C" void kernel_launch(void* const* d_in, const int* in_sizes, int n_in,
                              void* d_out, int out_size) {
    const float* x  = (const float*)d_in[0];
    const int*   ei = (const int*)d_in[1];
    const float* W1 = (const float*)d_in[2];
    const float* b1 = (const float*)d_in[3];
    const float* W2 = (const float*)d_in[4];
    const float* b2 = (const float*)d_in[5];
    const float* W3 = (const float*)d_in[6];
    const float* b3 = (const float*)d_in[7];
    float* out = (float*)d_out;

    static cudaStream_t s2 = nullptr;
    static cudaEvent_t evFork = nullptr, evCsr = nullptr;
    static int grid2 = 0;
    if (!s2) {
        cudaStreamCreateWithFlags(&s2, cudaStreamNonBlocking);
        cudaEventCreateWithFlags(&evFork, cudaEventDisableTiming);
        cudaEventCreateWithFlags(&evCsr, cudaEventDisableTiming);
        int nsm = 0;
        cudaDeviceGetAttribute(&nsm, cudaDevAttrMultiProcessorCount, 0);
        grid2 = 2 * nsm;
        cudaFuncSetAttribute(k_edge_pers, cudaFuncAttributeMaxDynamicSharedMemorySize, EDGE_SMEM);
        cudaFuncSetAttribute(k_node_hmma, cudaFuncAttributeMaxDynamicSharedMemorySize, NODE_SMEM);
    }

    // default stream: zero out + dst histogram (g_cnt zeroed by prior run / load)
    k_init<<<(NN * 128 / 4 + 255) / 256, 256>>>((float4*)out, NN * 128 / 4, ei);

    // fork: scan + scatter on s2
    cudaEventRecord(evFork, 0);
    cudaStreamWaitEvent(s2, evFork, 0);
    k_scan<<<1, 1024, 0, s2>>>();
    k_scatter<<<NE / 256, 256, 0, s2>>>(ei);
    cudaEventRecord(evCsr, s2);

    // default stream: weights -> node GEMM (concurrent with scan/scatter)
    k_prep_w<<<192, 256>>>(W1, b1, W2, b2, W3);
    k_node_hmma<<<(NN + 63) / 64, 256, NODE_SMEM>>>(x);

    // join: edge GEMM needs both PQ and CSR
    cudaStreamWaitEvent(0, evCsr, 0);
    k_edge_pers<<<grid2, 256, EDGE_SMEM>>>(b3, out);
}